// round 4
// baseline (speedup 1.0000x reference)
#include <cuda_runtime.h>

// ---------------------------------------------------------------------------
// Attention_87557203296748 — full MHA block, fp32 baseline.
//   1) qkv = x @ w_qkv^T        (8192 x 3072 x 1024), scatter to Q/K/V [B,H,N,HD]
//   2) flash attention per (b,h), q-tile 64, kv-tile 64, online softmax
//   3) out = attn_out @ w_proj^T + b_proj  (8192 x 1024 x 1024)
// All fp32 -> rel_err ~1e-6. Three kernel launches, graph-capturable,
// scratch in __device__ globals (no allocations).
// ---------------------------------------------------------------------------

#define BATCH  4
#define SEQ    2048
#define DIM    1024
#define NH     16
#define HDIM   64
#define QSCALE 0.125f          // HD^-0.5 = 1/8
#define MTOT   (BATCH * SEQ)   // 8192

__device__ float g_q [(size_t)BATCH * NH * SEQ * HDIM];  // 32 MB
__device__ float g_k [(size_t)BATCH * NH * SEQ * HDIM];  // 32 MB
__device__ float g_v [(size_t)BATCH * NH * SEQ * HDIM];  // 32 MB
__device__ float g_ao[(size_t)MTOT * DIM];               // 32 MB, [B,N,H,HD] = [8192,1024]

// ---------------------------------------------------------------------------
// Tiled SGEMM, C[m,e] = sum_k A[m,k] * B[e,k]  (both row-major, K-contiguous).
// 128x128x16 tile, 256 threads, 8x8 per thread.
// MODE 0: A = x, B = w_qkv -> scatter into g_q/g_k/g_v (Q scaled).
// MODE 1: A = g_ao, B = w_proj -> Cout = C + bias.
// ---------------------------------------------------------------------------
template <int MODE>
__launch_bounds__(256, 2)
__global__ void gemm_nt_kernel(const float* __restrict__ Ain,
                               const float* __restrict__ Bw,
                               const float* __restrict__ bias,
                               float* __restrict__ Cout)
{
    const int K = 1024;
    __shared__ float As[16 * 132];   // [k][m], padded stride 132
    __shared__ float Bs[16 * 132];   // [k][e]

    const float* A = (MODE == 0) ? Ain : g_ao;

    const int tid = threadIdx.x;
    const int ty  = tid >> 4;        // 0..15, M direction
    const int tx  = tid & 15;        // 0..15, E direction
    const int m0  = blockIdx.y * 128;
    const int e0  = blockIdx.x * 128;

    float acc[8][8];
#pragma unroll
    for (int i = 0; i < 8; i++)
#pragma unroll
        for (int j = 0; j < 8; j++) acc[i][j] = 0.0f;

    for (int k0 = 0; k0 < K; k0 += 16) {
#pragma unroll
        for (int i = 0; i < 2; i++) {
            int id = tid + i * 256;          // 0..511
            int r  = id >> 2;                // 0..127 (tile row)
            int c4 = (id & 3) << 2;          // 0,4,8,12 (k offset)
            float4 va = *(const float4*)(A  + (size_t)(m0 + r) * K + k0 + c4);
            As[(c4 + 0) * 132 + r] = va.x;
            As[(c4 + 1) * 132 + r] = va.y;
            As[(c4 + 2) * 132 + r] = va.z;
            As[(c4 + 3) * 132 + r] = va.w;
            float4 vb = *(const float4*)(Bw + (size_t)(e0 + r) * K + k0 + c4);
            Bs[(c4 + 0) * 132 + r] = vb.x;
            Bs[(c4 + 1) * 132 + r] = vb.y;
            Bs[(c4 + 2) * 132 + r] = vb.z;
            Bs[(c4 + 3) * 132 + r] = vb.w;
        }
        __syncthreads();

#pragma unroll
        for (int kk = 0; kk < 16; kk++) {
            float a[8], b[8];
            *(float4*)&a[0] = *(float4*)&As[kk * 132 + ty * 8];
            *(float4*)&a[4] = *(float4*)&As[kk * 132 + ty * 8 + 4];
            *(float4*)&b[0] = *(float4*)&Bs[kk * 132 + tx * 8];
            *(float4*)&b[4] = *(float4*)&Bs[kk * 132 + tx * 8 + 4];
#pragma unroll
            for (int i = 0; i < 8; i++)
#pragma unroll
                for (int j = 0; j < 8; j++)
                    acc[i][j] = fmaf(a[i], b[j], acc[i][j]);
        }
        __syncthreads();
    }

    if (MODE == 0) {
        // e in [0,3072): c = e/1024 selects Q/K/V, h = (e%1024)/64, hd = e%64.
        // Each thread's 8 e's stay inside one (c,h) block (start % 8 == 0).
        const int e_base = e0 + tx * 8;
        const int c   = e_base >> 10;
        const int rem = e_base & 1023;
        const int h   = rem >> 6;
        const int hd0 = rem & 63;
        const float mul = (c == 0) ? QSCALE : 1.0f;
        float* buf = (c == 0) ? g_q : ((c == 1) ? g_k : g_v);
#pragma unroll
        for (int i = 0; i < 8; i++) {
            int m  = m0 + ty * 8 + i;
            int b_ = m >> 11;        // / 2048
            int n  = m & 2047;
            float* p = buf + ((size_t)((b_ * NH + h) * SEQ + n)) * HDIM + hd0;
            float4 v0 = make_float4(acc[i][0] * mul, acc[i][1] * mul,
                                    acc[i][2] * mul, acc[i][3] * mul);
            float4 v1 = make_float4(acc[i][4] * mul, acc[i][5] * mul,
                                    acc[i][6] * mul, acc[i][7] * mul);
            *(float4*)p       = v0;
            *(float4*)(p + 4) = v1;
        }
    } else {
        const int e_base = e0 + tx * 8;
        float4 bb0 = *(const float4*)(bias + e_base);
        float4 bb1 = *(const float4*)(bias + e_base + 4);
#pragma unroll
        for (int i = 0; i < 8; i++) {
            int m = m0 + ty * 8 + i;
            float* p = Cout + (size_t)m * 1024 + e_base;
            float4 v0 = make_float4(acc[i][0] + bb0.x, acc[i][1] + bb0.y,
                                    acc[i][2] + bb0.z, acc[i][3] + bb0.w);
            float4 v1 = make_float4(acc[i][4] + bb1.x, acc[i][5] + bb1.y,
                                    acc[i][6] + bb1.z, acc[i][7] + bb1.w);
            *(float4*)p       = v0;
            *(float4*)(p + 4) = v1;
        }
    }
}

// ---------------------------------------------------------------------------
// Flash attention, fp32. Grid: (32 q-tiles, 64 bh). 256 threads.
// Thread (ty,tx): ty=tid/16 owns q-rows 4ty..4ty+3, tx=tid%16 owns cols 4tx..4tx+3.
// The 16 lanes of one q-row group are contiguous within a warp -> shfl_xor(<=8)
// reduces rows. Q and K stored TRANSPOSED in smem; P stored transposed into the
// K buffer -> every inner-loop read is a conflict-free LDS.128 (2 loads / 16 FMA).
// ---------------------------------------------------------------------------
#define KP_STRIDE 68
#define FLASH_SMEM_BYTES ((64 * 64 + 64 * KP_STRIDE + 64 * 64) * 4)   // 50176

__launch_bounds__(256, 2)
__global__ void flash_kernel()
{
    extern __shared__ float sm[];
    float* QsT = sm;                       // [d=64][q=64], stride 64
    float* KP  = sm + 64 * 64;             // K^T [d][k] then P^T [k][q], stride 68
    float* Vs  = KP + 64 * KP_STRIDE;      // [k=64][d=64], stride 64

    const int tid = threadIdx.x;
    const int ty  = tid >> 4;
    const int tx  = tid & 15;
    const int qt  = blockIdx.x;            // 0..31
    const int bh  = blockIdx.y;            // 0..63

    const float* Qg = g_q + (size_t)bh * SEQ * HDIM + (size_t)qt * 64 * HDIM;
    const float* Kg = g_k + (size_t)bh * SEQ * HDIM;
    const float* Vg = g_v + (size_t)bh * SEQ * HDIM;

    // Load Q tile transposed (once per CTA; store conflicts amortized away).
#pragma unroll
    for (int i = 0; i < 4; i++) {
        int id = tid + i * 256;
        int r  = id >> 4;                  // 0..63 q-row
        int c  = (id & 15) << 2;           // 0..60 d
        float4 q4 = *(const float4*)(Qg + (size_t)r * HDIM + c);
        QsT[(c + 0) * 64 + r] = q4.x;
        QsT[(c + 1) * 64 + r] = q4.y;
        QsT[(c + 2) * 64 + r] = q4.z;
        QsT[(c + 3) * 64 + r] = q4.w;
    }

    float m_i[4], l_i[4], o[4][4];
#pragma unroll
    for (int i = 0; i < 4; i++) {
        m_i[i] = -1e30f;
        l_i[i] = 0.0f;
#pragma unroll
        for (int j = 0; j < 4; j++) o[i][j] = 0.0f;
    }

    for (int kt = 0; kt < SEQ / 64; kt++) {
        __syncthreads();   // previous PV reads of KP/Vs complete

        const float* kg = Kg + (size_t)kt * 64 * HDIM;
        const float* vg = Vg + (size_t)kt * 64 * HDIM;
#pragma unroll
        for (int i = 0; i < 4; i++) {
            int id = tid + i * 256;
            int r  = id >> 4;
            int c  = (id & 15) << 2;
            float4 k4 = *(const float4*)(kg + (size_t)r * HDIM + c);
            KP[(c + 0) * KP_STRIDE + r] = k4.x;
            KP[(c + 1) * KP_STRIDE + r] = k4.y;
            KP[(c + 2) * KP_STRIDE + r] = k4.z;
            KP[(c + 3) * KP_STRIDE + r] = k4.w;
            *(float4*)&Vs[r * 64 + c] = *(const float4*)(vg + (size_t)r * HDIM + c);
        }
        __syncthreads();

        // S[i][j] = sum_d Q[4ty+i][d] * K[4tx+j][d]
        float s[4][4];
#pragma unroll
        for (int i = 0; i < 4; i++)
#pragma unroll
            for (int j = 0; j < 4; j++) s[i][j] = 0.0f;

#pragma unroll 8
        for (int d = 0; d < 64; d++) {
            float4 qf = *(float4*)&QsT[d * 64 + (ty << 2)];
            float4 kf = *(float4*)&KP [d * KP_STRIDE + (tx << 2)];
            s[0][0] = fmaf(qf.x, kf.x, s[0][0]); s[0][1] = fmaf(qf.x, kf.y, s[0][1]);
            s[0][2] = fmaf(qf.x, kf.z, s[0][2]); s[0][3] = fmaf(qf.x, kf.w, s[0][3]);
            s[1][0] = fmaf(qf.y, kf.x, s[1][0]); s[1][1] = fmaf(qf.y, kf.y, s[1][1]);
            s[1][2] = fmaf(qf.y, kf.z, s[1][2]); s[1][3] = fmaf(qf.y, kf.w, s[1][3]);
            s[2][0] = fmaf(qf.z, kf.x, s[2][0]); s[2][1] = fmaf(qf.z, kf.y, s[2][1]);
            s[2][2] = fmaf(qf.z, kf.z, s[2][2]); s[2][3] = fmaf(qf.z, kf.w, s[2][3]);
            s[3][0] = fmaf(qf.w, kf.x, s[3][0]); s[3][1] = fmaf(qf.w, kf.y, s[3][1]);
            s[3][2] = fmaf(qf.w, kf.z, s[3][2]); s[3][3] = fmaf(qf.w, kf.w, s[3][3]);
        }

        // Online softmax per q-row (16-lane reductions).
        float p[4][4];
#pragma unroll
        for (int i = 0; i < 4; i++) {
            float mx = fmaxf(fmaxf(s[i][0], s[i][1]), fmaxf(s[i][2], s[i][3]));
#pragma unroll
            for (int w = 8; w >= 1; w >>= 1)
                mx = fmaxf(mx, __shfl_xor_sync(0xffffffffu, mx, w));
            float mnew = fmaxf(m_i[i], mx);
            float corr = __expf(m_i[i] - mnew);
            m_i[i] = mnew;
            float rs = 0.0f;
#pragma unroll
            for (int j = 0; j < 4; j++) {
                p[i][j] = __expf(s[i][j] - mnew);
                rs += p[i][j];
            }
#pragma unroll
            for (int w = 8; w >= 1; w >>= 1)
                rs += __shfl_xor_sync(0xffffffffu, rs, w);
            l_i[i] = l_i[i] * corr + rs;
#pragma unroll
            for (int j = 0; j < 4; j++) o[i][j] *= corr;
        }

        __syncthreads();   // all lanes done reading KP as K^T
        // Store P^T into KP: P[4ty+i][4tx+j] -> KP[(4tx+j)*68 + 4ty+i]
#pragma unroll
        for (int j = 0; j < 4; j++) {
            float4 pv = make_float4(p[0][j], p[1][j], p[2][j], p[3][j]);
            *(float4*)&KP[((tx << 2) + j) * KP_STRIDE + (ty << 2)] = pv;
        }
        __syncthreads();

        // O[i][j] += sum_k P[4ty+i][k] * V[k][4tx+j]
#pragma unroll 8
        for (int k = 0; k < 64; k++) {
            float4 pf = *(float4*)&KP[k * KP_STRIDE + (ty << 2)];
            float4 vf = *(float4*)&Vs[k * 64 + (tx << 2)];
            o[0][0] = fmaf(pf.x, vf.x, o[0][0]); o[0][1] = fmaf(pf.x, vf.y, o[0][1]);
            o[0][2] = fmaf(pf.x, vf.z, o[0][2]); o[0][3] = fmaf(pf.x, vf.w, o[0][3]);
            o[1][0] = fmaf(pf.y, vf.x, o[1][0]); o[1][1] = fmaf(pf.y, vf.y, o[1][1]);
            o[1][2] = fmaf(pf.y, vf.z, o[1][2]); o[1][3] = fmaf(pf.y, vf.w, o[1][3]);
            o[2][0] = fmaf(pf.z, vf.x, o[2][0]); o[2][1] = fmaf(pf.z, vf.y, o[2][1]);
            o[2][2] = fmaf(pf.z, vf.z, o[2][2]); o[2][3] = fmaf(pf.z, vf.w, o[2][3]);
            o[3][0] = fmaf(pf.w, vf.x, o[3][0]); o[3][1] = fmaf(pf.w, vf.y, o[3][1]);
            o[3][2] = fmaf(pf.w, vf.z, o[3][2]); o[3][3] = fmaf(pf.w, vf.w, o[3][3]);
        }
    }

    // Normalize and write to g_ao in [B, N, H*HD] layout (GEMM3 input).
    const int b_ = bh >> 4;
    const int h  = bh & 15;
#pragma unroll
    for (int i = 0; i < 4; i++) {
        int n = qt * 64 + (ty << 2) + i;
        float inv = 1.0f / l_i[i];
        float* p = g_ao + ((size_t)(b_ * SEQ + n)) * DIM + h * HDIM + (tx << 2);
        *(float4*)p = make_float4(o[i][0] * inv, o[i][1] * inv,
                                  o[i][2] * inv, o[i][3] * inv);
    }
}

// ---------------------------------------------------------------------------
// Launch: x, w_qkv, w_proj, b_proj (metadata order). Output fp32 [B,N,D].
// ---------------------------------------------------------------------------
extern "C" void kernel_launch(void* const* d_in, const int* in_sizes, int n_in,
                              void* d_out, int out_size)
{
    (void)in_sizes; (void)n_in; (void)out_size;
    const float* x      = (const float*)d_in[0];
    const float* w_qkv  = (const float*)d_in[1];
    const float* w_proj = (const float*)d_in[2];
    const float* b_proj = (const float*)d_in[3];
    float* out = (float*)d_out;

    // 1) QKV projection + scatter (+Q scale)
    gemm_nt_kernel<0><<<dim3(3072 / 128, MTOT / 128), 256>>>(x, w_qkv, nullptr, nullptr);

    // 2) Flash attention (50 KB dynamic smem -> needs opt-in; idempotent, not a stream op)
    cudaFuncSetAttribute(flash_kernel, cudaFuncAttributeMaxDynamicSharedMemorySize,
                         FLASH_SMEM_BYTES);
    flash_kernel<<<dim3(SEQ / 64, BATCH * NH), 256, FLASH_SMEM_BYTES>>>();

    // 3) Output projection + bias
    gemm_nt_kernel<1><<<dim3(1024 / 128, MTOT / 128), 256>>>(x, w_proj, b_proj, out);
}

// round 5
// speedup vs baseline: 1.0000x; 1.0000x over previous
#include <cuda_runtime.h>

// ---------------------------------------------------------------------------
// Attention_87557203296748 — full MHA block, fp32 baseline.
//   1) qkv = x @ w_qkv^T        (8192 x 3072 x 1024), scatter to Q/K/V [B,H,N,HD]
//   2) flash attention per (b,h), q-tile 64, kv-tile 64, online softmax
//   3) out = attn_out @ w_proj^T + b_proj  (8192 x 1024 x 1024)
// All fp32 -> rel_err ~1e-6. Three kernel launches, graph-capturable,
// scratch in __device__ globals (no allocations).
// ---------------------------------------------------------------------------

#define BATCH  4
#define SEQ    2048
#define DIM    1024
#define NH     16
#define HDIM   64
#define QSCALE 0.125f          // HD^-0.5 = 1/8
#define MTOT   (BATCH * SEQ)   // 8192

__device__ float g_q [(size_t)BATCH * NH * SEQ * HDIM];  // 32 MB
__device__ float g_k [(size_t)BATCH * NH * SEQ * HDIM];  // 32 MB
__device__ float g_v [(size_t)BATCH * NH * SEQ * HDIM];  // 32 MB
__device__ float g_ao[(size_t)MTOT * DIM];               // 32 MB, [B,N,H,HD] = [8192,1024]

// ---------------------------------------------------------------------------
// Tiled SGEMM, C[m,e] = sum_k A[m,k] * B[e,k]  (both row-major, K-contiguous).
// 128x128x16 tile, 256 threads, 8x8 per thread.
// MODE 0: A = x, B = w_qkv -> scatter into g_q/g_k/g_v (Q scaled).
// MODE 1: A = g_ao, B = w_proj -> Cout = C + bias.
// ---------------------------------------------------------------------------
template <int MODE>
__launch_bounds__(256, 2)
__global__ void gemm_nt_kernel(const float* __restrict__ Ain,
                               const float* __restrict__ Bw,
                               const float* __restrict__ bias,
                               float* __restrict__ Cout)
{
    const int K = 1024;
    __shared__ float As[16 * 132];   // [k][m], padded stride 132
    __shared__ float Bs[16 * 132];   // [k][e]

    const float* A = (MODE == 0) ? Ain : g_ao;

    const int tid = threadIdx.x;
    const int ty  = tid >> 4;        // 0..15, M direction
    const int tx  = tid & 15;        // 0..15, E direction
    const int m0  = blockIdx.y * 128;
    const int e0  = blockIdx.x * 128;

    float acc[8][8];
#pragma unroll
    for (int i = 0; i < 8; i++)
#pragma unroll
        for (int j = 0; j < 8; j++) acc[i][j] = 0.0f;

    for (int k0 = 0; k0 < K; k0 += 16) {
#pragma unroll
        for (int i = 0; i < 2; i++) {
            int id = tid + i * 256;          // 0..511
            int r  = id >> 2;                // 0..127 (tile row)
            int c4 = (id & 3) << 2;          // 0,4,8,12 (k offset)
            float4 va = *(const float4*)(A  + (size_t)(m0 + r) * K + k0 + c4);
            As[(c4 + 0) * 132 + r] = va.x;
            As[(c4 + 1) * 132 + r] = va.y;
            As[(c4 + 2) * 132 + r] = va.z;
            As[(c4 + 3) * 132 + r] = va.w;
            float4 vb = *(const float4*)(Bw + (size_t)(e0 + r) * K + k0 + c4);
            Bs[(c4 + 0) * 132 + r] = vb.x;
            Bs[(c4 + 1) * 132 + r] = vb.y;
            Bs[(c4 + 2) * 132 + r] = vb.z;
            Bs[(c4 + 3) * 132 + r] = vb.w;
        }
        __syncthreads();

#pragma unroll
        for (int kk = 0; kk < 16; kk++) {
            float a[8], b[8];
            *(float4*)&a[0] = *(float4*)&As[kk * 132 + ty * 8];
            *(float4*)&a[4] = *(float4*)&As[kk * 132 + ty * 8 + 4];
            *(float4*)&b[0] = *(float4*)&Bs[kk * 132 + tx * 8];
            *(float4*)&b[4] = *(float4*)&Bs[kk * 132 + tx * 8 + 4];
#pragma unroll
            for (int i = 0; i < 8; i++)
#pragma unroll
                for (int j = 0; j < 8; j++)
                    acc[i][j] = fmaf(a[i], b[j], acc[i][j]);
        }
        __syncthreads();
    }

    if (MODE == 0) {
        // e in [0,3072): c = e/1024 selects Q/K/V, h = (e%1024)/64, hd = e%64.
        // Each thread's 8 e's stay inside one (c,h) block (start % 8 == 0).
        const int e_base = e0 + tx * 8;
        const int c   = e_base >> 10;
        const int rem = e_base & 1023;
        const int h   = rem >> 6;
        const int hd0 = rem & 63;
        const float mul = (c == 0) ? QSCALE : 1.0f;
        float* buf = (c == 0) ? g_q : ((c == 1) ? g_k : g_v);
#pragma unroll
        for (int i = 0; i < 8; i++) {
            int m  = m0 + ty * 8 + i;
            int b_ = m >> 11;        // / 2048
            int n  = m & 2047;
            float* p = buf + ((size_t)((b_ * NH + h) * SEQ + n)) * HDIM + hd0;
            float4 v0 = make_float4(acc[i][0] * mul, acc[i][1] * mul,
                                    acc[i][2] * mul, acc[i][3] * mul);
            float4 v1 = make_float4(acc[i][4] * mul, acc[i][5] * mul,
                                    acc[i][6] * mul, acc[i][7] * mul);
            *(float4*)p       = v0;
            *(float4*)(p + 4) = v1;
        }
    } else {
        const int e_base = e0 + tx * 8;
        float4 bb0 = *(const float4*)(bias + e_base);
        float4 bb1 = *(const float4*)(bias + e_base + 4);
#pragma unroll
        for (int i = 0; i < 8; i++) {
            int m = m0 + ty * 8 + i;
            float* p = Cout + (size_t)m * 1024 + e_base;
            float4 v0 = make_float4(acc[i][0] + bb0.x, acc[i][1] + bb0.y,
                                    acc[i][2] + bb0.z, acc[i][3] + bb0.w);
            float4 v1 = make_float4(acc[i][4] + bb1.x, acc[i][5] + bb1.y,
                                    acc[i][6] + bb1.z, acc[i][7] + bb1.w);
            *(float4*)p       = v0;
            *(float4*)(p + 4) = v1;
        }
    }
}

// ---------------------------------------------------------------------------
// Flash attention, fp32. Grid: (32 q-tiles, 64 bh). 256 threads.
// Thread (ty,tx): ty=tid/16 owns q-rows 4ty..4ty+3, tx=tid%16 owns cols 4tx..4tx+3.
// The 16 lanes of one q-row group are contiguous within a warp -> shfl_xor(<=8)
// reduces rows. Q and K stored TRANSPOSED in smem; P stored transposed into the
// K buffer -> every inner-loop read is a conflict-free LDS.128 (2 loads / 16 FMA).
// ---------------------------------------------------------------------------
#define KP_STRIDE 68
#define FLASH_SMEM_BYTES ((64 * 64 + 64 * KP_STRIDE + 64 * 64) * 4)   // 50176

__launch_bounds__(256, 2)
__global__ void flash_kernel()
{
    extern __shared__ float sm[];
    float* QsT = sm;                       // [d=64][q=64], stride 64
    float* KP  = sm + 64 * 64;             // K^T [d][k] then P^T [k][q], stride 68
    float* Vs  = KP + 64 * KP_STRIDE;      // [k=64][d=64], stride 64

    const int tid = threadIdx.x;
    const int ty  = tid >> 4;
    const int tx  = tid & 15;
    const int qt  = blockIdx.x;            // 0..31
    const int bh  = blockIdx.y;            // 0..63

    const float* Qg = g_q + (size_t)bh * SEQ * HDIM + (size_t)qt * 64 * HDIM;
    const float* Kg = g_k + (size_t)bh * SEQ * HDIM;
    const float* Vg = g_v + (size_t)bh * SEQ * HDIM;

    // Load Q tile transposed (once per CTA; store conflicts amortized away).
#pragma unroll
    for (int i = 0; i < 4; i++) {
        int id = tid + i * 256;
        int r  = id >> 4;                  // 0..63 q-row
        int c  = (id & 15) << 2;           // 0..60 d
        float4 q4 = *(const float4*)(Qg + (size_t)r * HDIM + c);
        QsT[(c + 0) * 64 + r] = q4.x;
        QsT[(c + 1) * 64 + r] = q4.y;
        QsT[(c + 2) * 64 + r] = q4.z;
        QsT[(c + 3) * 64 + r] = q4.w;
    }

    float m_i[4], l_i[4], o[4][4];
#pragma unroll
    for (int i = 0; i < 4; i++) {
        m_i[i] = -1e30f;
        l_i[i] = 0.0f;
#pragma unroll
        for (int j = 0; j < 4; j++) o[i][j] = 0.0f;
    }

    for (int kt = 0; kt < SEQ / 64; kt++) {
        __syncthreads();   // previous PV reads of KP/Vs complete

        const float* kg = Kg + (size_t)kt * 64 * HDIM;
        const float* vg = Vg + (size_t)kt * 64 * HDIM;
#pragma unroll
        for (int i = 0; i < 4; i++) {
            int id = tid + i * 256;
            int r  = id >> 4;
            int c  = (id & 15) << 2;
            float4 k4 = *(const float4*)(kg + (size_t)r * HDIM + c);
            KP[(c + 0) * KP_STRIDE + r] = k4.x;
            KP[(c + 1) * KP_STRIDE + r] = k4.y;
            KP[(c + 2) * KP_STRIDE + r] = k4.z;
            KP[(c + 3) * KP_STRIDE + r] = k4.w;
            *(float4*)&Vs[r * 64 + c] = *(const float4*)(vg + (size_t)r * HDIM + c);
        }
        __syncthreads();

        // S[i][j] = sum_d Q[4ty+i][d] * K[4tx+j][d]
        float s[4][4];
#pragma unroll
        for (int i = 0; i < 4; i++)
#pragma unroll
            for (int j = 0; j < 4; j++) s[i][j] = 0.0f;

#pragma unroll 8
        for (int d = 0; d < 64; d++) {
            float4 qf = *(float4*)&QsT[d * 64 + (ty << 2)];
            float4 kf = *(float4*)&KP [d * KP_STRIDE + (tx << 2)];
            s[0][0] = fmaf(qf.x, kf.x, s[0][0]); s[0][1] = fmaf(qf.x, kf.y, s[0][1]);
            s[0][2] = fmaf(qf.x, kf.z, s[0][2]); s[0][3] = fmaf(qf.x, kf.w, s[0][3]);
            s[1][0] = fmaf(qf.y, kf.x, s[1][0]); s[1][1] = fmaf(qf.y, kf.y, s[1][1]);
            s[1][2] = fmaf(qf.y, kf.z, s[1][2]); s[1][3] = fmaf(qf.y, kf.w, s[1][3]);
            s[2][0] = fmaf(qf.z, kf.x, s[2][0]); s[2][1] = fmaf(qf.z, kf.y, s[2][1]);
            s[2][2] = fmaf(qf.z, kf.z, s[2][2]); s[2][3] = fmaf(qf.z, kf.w, s[2][3]);
            s[3][0] = fmaf(qf.w, kf.x, s[3][0]); s[3][1] = fmaf(qf.w, kf.y, s[3][1]);
            s[3][2] = fmaf(qf.w, kf.z, s[3][2]); s[3][3] = fmaf(qf.w, kf.w, s[3][3]);
        }

        // Online softmax per q-row (16-lane reductions).
        float p[4][4];
#pragma unroll
        for (int i = 0; i < 4; i++) {
            float mx = fmaxf(fmaxf(s[i][0], s[i][1]), fmaxf(s[i][2], s[i][3]));
#pragma unroll
            for (int w = 8; w >= 1; w >>= 1)
                mx = fmaxf(mx, __shfl_xor_sync(0xffffffffu, mx, w));
            float mnew = fmaxf(m_i[i], mx);
            float corr = __expf(m_i[i] - mnew);
            m_i[i] = mnew;
            float rs = 0.0f;
#pragma unroll
            for (int j = 0; j < 4; j++) {
                p[i][j] = __expf(s[i][j] - mnew);
                rs += p[i][j];
            }
#pragma unroll
            for (int w = 8; w >= 1; w >>= 1)
                rs += __shfl_xor_sync(0xffffffffu, rs, w);
            l_i[i] = l_i[i] * corr + rs;
#pragma unroll
            for (int j = 0; j < 4; j++) o[i][j] *= corr;
        }

        __syncthreads();   // all lanes done reading KP as K^T
        // Store P^T into KP: P[4ty+i][4tx+j] -> KP[(4tx+j)*68 + 4ty+i]
#pragma unroll
        for (int j = 0; j < 4; j++) {
            float4 pv = make_float4(p[0][j], p[1][j], p[2][j], p[3][j]);
            *(float4*)&KP[((tx << 2) + j) * KP_STRIDE + (ty << 2)] = pv;
        }
        __syncthreads();

        // O[i][j] += sum_k P[4ty+i][k] * V[k][4tx+j]
#pragma unroll 8
        for (int k = 0; k < 64; k++) {
            float4 pf = *(float4*)&KP[k * KP_STRIDE + (ty << 2)];
            float4 vf = *(float4*)&Vs[k * 64 + (tx << 2)];
            o[0][0] = fmaf(pf.x, vf.x, o[0][0]); o[0][1] = fmaf(pf.x, vf.y, o[0][1]);
            o[0][2] = fmaf(pf.x, vf.z, o[0][2]); o[0][3] = fmaf(pf.x, vf.w, o[0][3]);
            o[1][0] = fmaf(pf.y, vf.x, o[1][0]); o[1][1] = fmaf(pf.y, vf.y, o[1][1]);
            o[1][2] = fmaf(pf.y, vf.z, o[1][2]); o[1][3] = fmaf(pf.y, vf.w, o[1][3]);
            o[2][0] = fmaf(pf.z, vf.x, o[2][0]); o[2][1] = fmaf(pf.z, vf.y, o[2][1]);
            o[2][2] = fmaf(pf.z, vf.z, o[2][2]); o[2][3] = fmaf(pf.z, vf.w, o[2][3]);
            o[3][0] = fmaf(pf.w, vf.x, o[3][0]); o[3][1] = fmaf(pf.w, vf.y, o[3][1]);
            o[3][2] = fmaf(pf.w, vf.z, o[3][2]); o[3][3] = fmaf(pf.w, vf.w, o[3][3]);
        }
    }

    // Normalize and write to g_ao in [B, N, H*HD] layout (GEMM3 input).
    const int b_ = bh >> 4;
    const int h  = bh & 15;
#pragma unroll
    for (int i = 0; i < 4; i++) {
        int n = qt * 64 + (ty << 2) + i;
        float inv = 1.0f / l_i[i];
        float* p = g_ao + ((size_t)(b_ * SEQ + n)) * DIM + h * HDIM + (tx << 2);
        *(float4*)p = make_float4(o[i][0] * inv, o[i][1] * inv,
                                  o[i][2] * inv, o[i][3] * inv);
    }
}

// ---------------------------------------------------------------------------
// Launch: x, w_qkv, w_proj, b_proj (metadata order). Output fp32 [B,N,D].
// ---------------------------------------------------------------------------
extern "C" void kernel_launch(void* const* d_in, const int* in_sizes, int n_in,
                              void* d_out, int out_size)
{
    (void)in_sizes; (void)n_in; (void)out_size;
    const float* x      = (const float*)d_in[0];
    const float* w_qkv  = (const float*)d_in[1];
    const float* w_proj = (const float*)d_in[2];
    const float* b_proj = (const float*)d_in[3];
    float* out = (float*)d_out;

    // 1) QKV projection + scatter (+Q scale)
    gemm_nt_kernel<0><<<dim3(3072 / 128, MTOT / 128), 256>>>(x, w_qkv, nullptr, nullptr);

    // 2) Flash attention (50 KB dynamic smem -> needs opt-in; idempotent, not a stream op)
    cudaFuncSetAttribute(flash_kernel, cudaFuncAttributeMaxDynamicSharedMemorySize,
                         FLASH_SMEM_BYTES);
    flash_kernel<<<dim3(SEQ / 64, BATCH * NH), 256, FLASH_SMEM_BYTES>>>();

    // 3) Output projection + bias
    gemm_nt_kernel<1><<<dim3(1024 / 128, MTOT / 128), 256>>>(x, w_proj, b_proj, out);
}